// round 9
// baseline (speedup 1.0000x reference)
#include <cuda_runtime.h>
#include <cuda.h>
#include <cstdint>

// RelateBatch: one-hot block structure of batch_object_map (obj_q = n//8)
// collapses both einsum chains to per-8x8 diagonal-block row/col reductions.
// Reads 8.4 MB instead of 537 MB.
// Round 9: persistent single-wave kernel. 128 CTAs x 8 units; the prologue
// issues ALL 32 TMA tile loads per CTA (whole 8.4 MB payload in flight
// chip-wide), one mbarrier per tile (used once, parity 0), warps consume
// tiles in arrival order. Fallback = round-7 LDG kernel.

#define EPSF 1e-12f

__device__ __forceinline__ float pnotf(float x, float a) {
    float xm = fminf(x, 0.0f);
    float e  = __expf(xm);
    float l  = __logf(fmaxf(1.0f - e, EPSF));
    return fmaf(a, l, (1.0f - a) * x);
}

__device__ __forceinline__ uint32_t smem_u32(const void* p) {
    return (uint32_t)__cvta_generic_to_shared(p);
}

__device__ __forceinline__ void mbar_wait0(uint32_t bar) {
    uint32_t done;
    asm volatile(
        "{\n\t.reg .pred pd;\n\t"
        "mbarrier.try_wait.parity.acquire.cta.shared::cta.b64 pd, [%1], 0;\n\t"
        "selp.b32 %0, 1, 0, pd;\n\t}"
        : "=r"(done) : "r"(bar) : "memory");
    if (!done) {
        asm volatile(
            "{\n\t.reg .pred P1;\n\t"
            "WL_%=:\n\t"
            "mbarrier.try_wait.parity.acquire.cta.shared::cta.b64 P1, [%0], 0, 0x989680;\n\t"
            "@P1 bra.uni WD_%=;\n\t"
            "bra.uni WL_%=;\n\t"
            "WD_%=:\n\t}"
            :: "r"(bar) : "memory");
    }
}

// Dynamic smem layout: 32 tiles x 512 floats (64KB), then 32 mbarriers.
static constexpr unsigned TILE_F   = 512;     // floats per tile (2KB)
static constexpr unsigned NTILES   = 32;      // 8 units x 4 tiles
static constexpr unsigned SMEM_SZ  = NTILES * TILE_F * 4 + NTILES * 8;

// -------------------------------------------------- persistent TMA kernel
__global__ __launch_bounds__(128) void relate_tma_persist(
    const __grid_constant__ CUtensorMap tmap,   // loglik as (4096, 512, 64)
    const float* __restrict__ log_prior,        // (64, 2, 512)
    const float* __restrict__ quant,            // (64, 2)
    float* __restrict__ out)                    // (64, 2, 512)
{
    constexpr unsigned N = 512;
    extern __shared__ __align__(1024) float smem[];
    uint64_t* mbar = reinterpret_cast<uint64_t*>(smem + NTILES * TILE_F);

    const unsigned tid = threadIdx.x;
    const unsigned b   = blockIdx.x;            // 0..127, 8 units each

    if (tid < NTILES) {
        asm volatile("mbarrier.init.shared.b64 [%0], %1;"
                     :: "r"(smem_u32(&mbar[tid])), "r"(1u) : "memory");
    }
    __syncthreads();

    if (tid == 0) {
        #pragma unroll
        for (unsigned s = 0; s < 8; s++) {
            const unsigned u    = b * 8u + s;   // unit 0..1023
            const unsigned p    = u >> 4;       // 0..63
            const unsigned quad = u & 15u;      // 0..15
            #pragma unroll
            for (unsigned t = 0; t < 4; t++) {
                const unsigned g  = quad * 4u + t;
                const unsigned ti = s * 4u + t;
                const uint32_t bar = smem_u32(&mbar[ti]);
                const uint32_t dst = smem_u32(&smem[ti * TILE_F]);
                asm volatile("mbarrier.arrive.expect_tx.shared.b64 _, [%0], %1;"
                             :: "r"(bar), "r"(2048u) : "memory");
                asm volatile(
                    "cp.async.bulk.tensor.3d.shared::cta.global.tile"
                    ".mbarrier::complete_tx::bytes [%0], [%1, {%2, %3, %4}], [%5];"
                    :: "r"(dst), "l"(&tmap),
                       "r"((int)(g * 64u)), "r"((int)(g * 8u)), "r"((int)p),
                       "r"(bar)
                    : "memory");
            }
        }
    }

    const unsigned wid  = tid >> 5;
    const unsigned lane = tid & 31u;
    const unsigned i0   = lane >> 3;        // 0..3
    const unsigned j    = lane & 7u;        // 0..7
    const unsigned r0   = i0;
    const unsigned r1   = i0 + 4u;

    #pragma unroll
    for (unsigned s = 0; s < 8; s++) {
        const unsigned u    = b * 8u + s;
        const unsigned p    = u >> 4;
        const unsigned quad = u & 15u;
        const unsigned g    = quad * 4u + wid;
        const unsigned m    = g * 8u + j;
        const unsigned ti   = s * 4u + wid;
        const float*   tb   = &smem[ti * TILE_F];

        mbar_wait0(smem_u32(&mbar[ti]));    // warp waits only on its tile

        const float q0 = quant[2u * p + 0u];
        const float q1 = quant[2u * p + 1u];
        const float lp0_r0 = log_prior[(p * 2u + 0u) * N + g * 8u + r0];
        const float lp0_r1 = log_prior[(p * 2u + 0u) * N + g * 8u + r1];
        const float lp1_m  = log_prior[(p * 2u + 1u) * N + m];

        float4 a0 = *reinterpret_cast<const float4*>(tb + r0 * 64u + j * 8u);
        float4 a1 = *reinterpret_cast<const float4*>(tb + r0 * 64u + j * 8u + 4u);
        float4 c0 = *reinterpret_cast<const float4*>(tb + r1 * 64u + j * 8u);
        float4 c1 = *reinterpret_cast<const float4*>(tb + r1 * 64u + j * 8u + 4u);

        float llv0 = fminf((((a0.x + a0.y) + (a0.z + a0.w)) +
                            ((a1.x + a1.y) + (a1.z + a1.w))) * 0.125f, 0.0f);
        float llv1 = fminf((((c0.x + c0.y) + (c0.z + c0.w)) +
                            ((c1.x + c1.y) + (c1.z + c1.w))) * 0.125f, 0.0f);

        const float d0 = (r0 == j) ? 0.0f : 1.0f;
        const float d1 = (r1 == j) ? 0.0f : 1.0f;

        float v0 = d0 * pnotf(llv0 + lp1_m, q1);
        float v1 = d1 * pnotf(llv1 + lp1_m, q1);
        float w0 = d0 * pnotf(llv0 + lp0_r0, q0);
        float w1 = d1 * pnotf(llv1 + lp0_r1, q0);

        #pragma unroll
        for (int d = 1; d < 8; d <<= 1) {
            v0 += __shfl_xor_sync(0xffffffffu, v0, d);
            v1 += __shfl_xor_sync(0xffffffffu, v1, d);
        }
        float wc = w0 + w1;
        wc += __shfl_xor_sync(0xffffffffu, wc, 8);
        wc += __shfl_xor_sync(0xffffffffu, wc, 16);

        if (j == 0u) {
            out[(p * 2u + 0u) * N + g * 8u + r0] = pnotf(v0, q1) + lp0_r0;
            out[(p * 2u + 0u) * N + g * 8u + r1] = pnotf(v1, q1) + lp0_r1;
        }
        if (i0 == 0u) {
            out[(p * 2u + 1u) * N + m] = pnotf(wc, q0) + lp1_m;
        }
    }
}

// ------------------------------------------------------ fallback LDG kernel
__global__ __launch_bounds__(128) void relate_batch_kernel(
    const float* __restrict__ log_prior,
    const float* __restrict__ loglik,
    const float* __restrict__ quant,
    float* __restrict__ out)
{
    constexpr unsigned N = 512;
    const unsigned p    = blockIdx.y;
    const unsigned g    = blockIdx.x * 4u + (threadIdx.x >> 5);
    const unsigned lane = threadIdx.x & 31u;
    const unsigned rh   = lane >> 4;
    const unsigned c    = lane & 15u;
    const unsigned ml   = c >> 1;
    const unsigned m    = g * 8u + ml;

    const float q0 = quant[2u * p + 0u];
    const float q1 = quant[2u * p + 1u];
    const float lp1_m = log_prior[(p * 2u + 1u) * N + m];

    float4 d[4];
    #pragma unroll
    for (int k = 0; k < 4; k++) {
        const unsigned row = rh + 2u * k;
        const unsigned base = ((p * N + g * 8u + row) * N + g * 8u) * 8u + c * 4u;
        d[k] = __ldcs(reinterpret_cast<const float4*>(loglik + base));
    }
    float lp0r[4];
    #pragma unroll
    for (int k = 0; k < 4; k++)
        lp0r[k] = log_prior[(p * 2u + 0u) * N + g * 8u + rh + 2u * k];

    float rs[4];
    float wl = 0.0f;
    #pragma unroll
    for (int k = 0; k < 4; k++) {
        float h = ((d[k].x + d[k].y) + (d[k].z + d[k].w));
        float full = h + __shfl_xor_sync(0xffffffffu, h, 1);
        float llv = fminf(full * 0.125f, 0.0f);
        const unsigned row = rh + 2u * k;
        float dm = (row == ml) ? 0.0f : 1.0f;
        rs[k] = dm * pnotf(llv + lp1_m, q1);
        wl   += dm * pnotf(llv + lp0r[k], q0);
    }
    #pragma unroll
    for (int dd = 2; dd < 16; dd <<= 1) {
        #pragma unroll
        for (int k = 0; k < 4; k++)
            rs[k] += __shfl_xor_sync(0xffffffffu, rs[k], dd);
    }
    if (c == 0u) {
        #pragma unroll
        for (int k = 0; k < 4; k++) {
            const unsigned n = g * 8u + rh + 2u * k;
            out[(p * 2u + 0u) * N + n] = pnotf(rs[k], q1) + lp0r[k];
        }
    }
    wl += __shfl_xor_sync(0xffffffffu, wl, 16);
    if (rh == 0u && (c & 1u) == 0u) {
        out[(p * 2u + 1u) * N + m] = pnotf(wl, q0) + lp1_m;
    }
}

// ---------------------------------------------------------------- host side
typedef CUresult (*EncodeTiledFn)(
    CUtensorMap*, CUtensorMapDataType, cuuint32_t, void*,
    const cuuint64_t*, const cuuint64_t*, const cuuint32_t*, const cuuint32_t*,
    CUtensorMapInterleave, CUtensorMapSwizzle, CUtensorMapL2promotion,
    CUtensorMapFloatOOBfill);

extern "C" void kernel_launch(void* const* d_in, const int* in_sizes, int n_in,
                              void* d_out, int out_size) {
    const float* log_prior = (const float*)d_in[0];   // (64,2,512)
    const float* loglik    = (const float*)d_in[1];   // (64,512,512,8)
    const float* quant     = (const float*)d_in[2];   // (64,2)
    float* out = (float*)d_out;                       // (64,2,512)

    void* fn = nullptr;
    cudaDriverEntryPointQueryResult qr = cudaDriverEntryPointSymbolNotFound;
    cudaGetDriverEntryPoint("cuTensorMapEncodeTiled", &fn,
                            cudaEnableDefault, &qr);

    bool tma_ok = false;
    CUtensorMap tmap;
    if (fn && qr == cudaDriverEntryPointSuccess) {
        // loglik (64,512,512,8) f32 viewed 3D: x = 4096 floats per n-row,
        // y = n (512, 16KB stride), z = p (64, 8.39MB stride).
        cuuint64_t dims[3]    = {4096ull, 512ull, 64ull};
        cuuint64_t strides[2] = {4096ull * 4ull, 512ull * 4096ull * 4ull};
        cuuint32_t box[3]     = {64u, 8u, 1u};
        cuuint32_t estr[3]    = {1u, 1u, 1u};
        CUresult r = ((EncodeTiledFn)fn)(
            &tmap, CU_TENSOR_MAP_DATA_TYPE_FLOAT32, 3, (void*)loglik,
            dims, strides, box, estr,
            CU_TENSOR_MAP_INTERLEAVE_NONE, CU_TENSOR_MAP_SWIZZLE_NONE,
            CU_TENSOR_MAP_L2_PROMOTION_L2_128B,
            CU_TENSOR_MAP_FLOAT_OOB_FILL_NONE);
        tma_ok = (r == CUDA_SUCCESS);
    }

    if (tma_ok) {
        static bool attr_done = false;
        // Setting the attribute is idempotent; call unconditionally to stay
        // deterministic under capture.
        cudaFuncSetAttribute(relate_tma_persist,
                             cudaFuncAttributeMaxDynamicSharedMemorySize,
                             (int)SMEM_SZ);
        (void)attr_done;
        relate_tma_persist<<<128, 128, SMEM_SZ>>>(tmap, log_prior, quant, out);
    } else {
        dim3 grid(16, 64);
        dim3 block(128);
        relate_batch_kernel<<<grid, block>>>(log_prior, loglik, quant, out);
    }
}

// round 11
// speedup vs baseline: 1.5577x; 1.5577x over previous
#include <cuda_runtime.h>
#include <cstdint>

// RelateBatch: one-hot block structure of batch_object_map (obj_q = n//8)
// collapses both einsum chains to per-8x8 diagonal-block row/col reductions.
// Reads 8.4 MB instead of 537 MB.
// Round 11: round-10 intent with the ptxas-legal form — L2::evict_last is
// only valid on 256-bit loads, so each lane loads one full 32B cell with a
// single ld.global.nc.L2::evict_last.v4.b64 (LDG.256). Warp = tile,
// round-3 reduction mapping, 4096 warps in 1024 CTAs.

#define EPSF 1e-12f

__device__ __forceinline__ float pnotf(float x, float a) {
    // a * log(max(1 - exp(min(x,0)), EPS)) + (1-a) * x
    float xm = fminf(x, 0.0f);
    float e  = __expf(xm);
    float l  = __logf(fmaxf(1.0f - e, EPSF));
    return fmaf(a, l, (1.0f - a) * x);
}

// 256-bit load of one 32B-aligned cell (8 floats), L2 evict-last.
__device__ __forceinline__ float ldg256_cellsum(const float* p) {
    unsigned long long a, b, c, d;
    asm volatile("ld.global.nc.L2::evict_last.v4.b64 {%0,%1,%2,%3}, [%4];"
                 : "=l"(a), "=l"(b), "=l"(c), "=l"(d) : "l"(p));
    float s0 = __uint_as_float((unsigned)a)         + __uint_as_float((unsigned)(a >> 32));
    float s1 = __uint_as_float((unsigned)b)         + __uint_as_float((unsigned)(b >> 32));
    float s2 = __uint_as_float((unsigned)c)         + __uint_as_float((unsigned)(c >> 32));
    float s3 = __uint_as_float((unsigned)d)         + __uint_as_float((unsigned)(d >> 32));
    return (s0 + s1) + (s2 + s3);
}

__global__ __launch_bounds__(128) void relate_batch_kernel(
    const float* __restrict__ log_prior,   // (64, 2, 512)
    const float* __restrict__ loglik,      // (64, 512, 512, 8)
    const float* __restrict__ quant,       // (64, 2)
    float* __restrict__ out)               // (64, 2, 512)
{
    constexpr unsigned N = 512;
    const unsigned p    = blockIdx.y;                           // 0..63
    const unsigned g    = blockIdx.x * 4u + (threadIdx.x >> 5); // tile 0..63
    const unsigned lane = threadIdx.x & 31u;
    const unsigned i0   = lane >> 3;                            // 0..3
    const unsigned j    = lane & 7u;                            // 0..7
    const unsigned r0   = i0;
    const unsigned r1   = i0 + 4u;
    const unsigned m    = g * 8u + j;                           // column object

    const float q0 = quant[2u * p + 0u];
    const float q1 = quant[2u * p + 1u];
    const float lp0_r0 = log_prior[(p * 2u + 0u) * N + g * 8u + r0];
    const float lp0_r1 = log_prior[(p * 2u + 0u) * N + g * 8u + r1];
    const float lp1_m  = log_prior[(p * 2u + 1u) * N + m];

    // Two independent LDG.256: cells (r0, j) and (r1, j). 8 consecutive
    // lanes cover 256B contiguous per row slice — fully dense sectors.
    const unsigned b0 = ((p * N + g * 8u + r0) * N + m) * 8u;
    const unsigned b1 = ((p * N + g * 8u + r1) * N + m) * 8u;
    float s0 = ldg256_cellsum(loglik + b0);
    float s1 = ldg256_cellsum(loglik + b1);

    float llv0 = fminf(s0 * 0.125f, 0.0f);   // min(mean_f, 0)
    float llv1 = fminf(s1 * 0.125f, 0.0f);

    const float d0 = (r0 == j) ? 0.0f : 1.0f;   // off_diag
    const float d1 = (r1 == j) ? 0.0f : 1.0f;

    float v0 = d0 * pnotf(llv0 + lp1_m, q1);    // row path (out0)
    float v1 = d1 * pnotf(llv1 + lp1_m, q1);
    float w0 = d0 * pnotf(llv0 + lp0_r0, q0);   // col path (out1)
    float w1 = d1 * pnotf(llv1 + lp0_r1, q0);

    // Row sums: butterfly over the 8-lane j-groups (two rows in parallel).
    #pragma unroll
    for (int d = 1; d < 8; d <<= 1) {
        v0 += __shfl_xor_sync(0xffffffffu, v0, d);
        v1 += __shfl_xor_sync(0xffffffffu, v1, d);
    }
    // Col sums: local pair (rows i0, i0+4), then butterfly across i-groups.
    float wc = w0 + w1;
    wc += __shfl_xor_sync(0xffffffffu, wc, 8);
    wc += __shfl_xor_sync(0xffffffffu, wc, 16);

    if (j == 0u) {
        out[(p * 2u + 0u) * N + g * 8u + r0] = pnotf(v0, q1) + lp0_r0;
        out[(p * 2u + 0u) * N + g * 8u + r1] = pnotf(v1, q1) + lp0_r1;
    }
    if (i0 == 0u) {
        out[(p * 2u + 1u) * N + m] = pnotf(wc, q0) + lp1_m;
    }
}

extern "C" void kernel_launch(void* const* d_in, const int* in_sizes, int n_in,
                              void* d_out, int out_size) {
    const float* log_prior = (const float*)d_in[0];   // (64,2,512)
    const float* loglik    = (const float*)d_in[1];   // (64,512,512,8)
    const float* quant     = (const float*)d_in[2];   // (64,2)
    float* out = (float*)d_out;                       // (64,2,512)

    dim3 grid(16, 64);   // 16 tile-quads x 64 batches = 1024 CTAs (4 warps ea)
    dim3 block(128);
    relate_batch_kernel<<<grid, block>>>(log_prior, loglik, quant, out);
}

// round 12
// speedup vs baseline: 1.5652x; 1.0048x over previous
#include <cuda_runtime.h>
#include <cuda.h>
#include <cstdint>

// RelateBatch: one-hot block structure of batch_object_map (obj_q = n//8)
// collapses both einsum chains to per-8x8 diagonal-block row/col reductions.
// Reads 8.4 MB instead of 537 MB.
// Round 12: the diagonal-block gather is LINEAR in (x, r, g, p):
//   addr = p*8388608 + g*131328 + r*16384 + x*4 bytes
// so a 4D tensor map with box {64,8,4,1} fetches a CTA's whole 8KB
// (4 tiles) in ONE TMA instruction, in exactly the tiles[4][512] layout.
// Compute = proven round-3 per-warp shuffle reduction.

#define EPSF 1e-12f

__device__ __forceinline__ float pnotf(float x, float a) {
    float xm = fminf(x, 0.0f);
    float e  = __expf(xm);
    float l  = __logf(fmaxf(1.0f - e, EPSF));
    return fmaf(a, l, (1.0f - a) * x);
}

__device__ __forceinline__ uint32_t smem_u32(const void* p) {
    return (uint32_t)__cvta_generic_to_shared(p);
}

// ---------------------------------------------------------------- TMA kernel
__global__ __launch_bounds__(128) void relate_tma_kernel(
    const __grid_constant__ CUtensorMap tmap,   // diagonal-linearized 4D view
    const float* __restrict__ log_prior,        // (64, 2, 512)
    const float* __restrict__ quant,            // (64, 2)
    float* __restrict__ out)                    // (64, 2, 512)
{
    constexpr unsigned N = 512;
    __shared__ __align__(1024) float tiles[4][512];   // 4 tiles x 2KB = 8KB
    __shared__ __align__(8) uint64_t mbar;

    const unsigned p   = blockIdx.y;            // 0..63
    const unsigned g0  = blockIdx.x * 4u;       // first tile of this CTA
    const unsigned tid = threadIdx.x;
    const uint32_t bar = smem_u32(&mbar);

    if (tid == 0) {
        asm volatile("mbarrier.init.shared.b64 [%0], %1;"
                     :: "r"(bar), "r"(1u) : "memory");
    }
    __syncthreads();

    if (tid == 0) {
        asm volatile("mbarrier.arrive.expect_tx.shared.b64 _, [%0], %1;"
                     :: "r"(bar), "r"(8192u) : "memory");
        // One 4D TMA: coords (x=0, y=0, z=g0, w=p), box {64,8,4,1}.
        asm volatile(
            "cp.async.bulk.tensor.4d.shared::cta.global.tile"
            ".mbarrier::complete_tx::bytes [%0], [%1, {%2, %3, %4, %5}], [%6];"
            :: "r"(smem_u32(&tiles[0][0])), "l"(&tmap),
               "r"(0), "r"(0), "r"((int)g0), "r"((int)p),
               "r"(bar)
            : "memory");
    }

    // All threads wait (acquire) for the 8KB.
    {
        uint32_t done;
        asm volatile(
            "{\n\t.reg .pred pd;\n\t"
            "mbarrier.try_wait.parity.acquire.cta.shared::cta.b64 pd, [%1], 0;\n\t"
            "selp.b32 %0, 1, 0, pd;\n\t}"
            : "=r"(done) : "r"(bar) : "memory");
        if (!done) {
            asm volatile(
                "{\n\t.reg .pred P1;\n\t"
                "WL_%=:\n\t"
                "mbarrier.try_wait.parity.acquire.cta.shared::cta.b64 P1, [%0], 0, 0x989680;\n\t"
                "@P1 bra.uni WD_%=;\n\t"
                "bra.uni WL_%=;\n\t"
                "WD_%=:\n\t}"
                :: "r"(bar) : "memory");
        }
    }

    // Per-warp compute: warp wid owns tile g0+wid (round-3 mapping).
    const unsigned wid  = tid >> 5;
    const unsigned lane = tid & 31u;
    const unsigned i0   = lane >> 3;        // 0..3
    const unsigned j    = lane & 7u;        // 0..7
    const unsigned r0   = i0;
    const unsigned r1   = i0 + 4u;
    const unsigned g    = g0 + wid;
    const unsigned m    = g * 8u + j;
    const float* tb = tiles[wid];

    const float q0 = quant[2u * p + 0u];
    const float q1 = quant[2u * p + 1u];
    const float lp0_r0 = log_prior[(p * 2u + 0u) * N + g * 8u + r0];
    const float lp0_r1 = log_prior[(p * 2u + 0u) * N + g * 8u + r1];
    const float lp1_m  = log_prior[(p * 2u + 1u) * N + m];

    float4 a0 = *reinterpret_cast<const float4*>(tb + r0 * 64u + j * 8u);
    float4 a1 = *reinterpret_cast<const float4*>(tb + r0 * 64u + j * 8u + 4u);
    float4 c0 = *reinterpret_cast<const float4*>(tb + r1 * 64u + j * 8u);
    float4 c1 = *reinterpret_cast<const float4*>(tb + r1 * 64u + j * 8u + 4u);

    float llv0 = fminf((((a0.x + a0.y) + (a0.z + a0.w)) +
                        ((a1.x + a1.y) + (a1.z + a1.w))) * 0.125f, 0.0f);
    float llv1 = fminf((((c0.x + c0.y) + (c0.z + c0.w)) +
                        ((c1.x + c1.y) + (c1.z + c1.w))) * 0.125f, 0.0f);

    const float d0 = (r0 == j) ? 0.0f : 1.0f;
    const float d1 = (r1 == j) ? 0.0f : 1.0f;

    float v0 = d0 * pnotf(llv0 + lp1_m, q1);
    float v1 = d1 * pnotf(llv1 + lp1_m, q1);
    float w0 = d0 * pnotf(llv0 + lp0_r0, q0);
    float w1 = d1 * pnotf(llv1 + lp0_r1, q0);

    #pragma unroll
    for (int d = 1; d < 8; d <<= 1) {
        v0 += __shfl_xor_sync(0xffffffffu, v0, d);
        v1 += __shfl_xor_sync(0xffffffffu, v1, d);
    }
    float wc = w0 + w1;
    wc += __shfl_xor_sync(0xffffffffu, wc, 8);
    wc += __shfl_xor_sync(0xffffffffu, wc, 16);

    if (j == 0u) {
        out[(p * 2u + 0u) * N + g * 8u + r0] = pnotf(v0, q1) + lp0_r0;
        out[(p * 2u + 0u) * N + g * 8u + r1] = pnotf(v1, q1) + lp0_r1;
    }
    if (i0 == 0u) {
        out[(p * 2u + 1u) * N + m] = pnotf(wc, q0) + lp1_m;
    }
}

// ------------------------------------------------------ fallback LDG kernel
__global__ __launch_bounds__(128) void relate_batch_kernel(
    const float* __restrict__ log_prior,
    const float* __restrict__ loglik,
    const float* __restrict__ quant,
    float* __restrict__ out)
{
    constexpr unsigned N = 512;
    const unsigned p    = blockIdx.y;
    const unsigned g    = blockIdx.x * 4u + (threadIdx.x >> 5);
    const unsigned lane = threadIdx.x & 31u;
    const unsigned rh   = lane >> 4;
    const unsigned c    = lane & 15u;
    const unsigned ml   = c >> 1;
    const unsigned m    = g * 8u + ml;

    const float q0 = quant[2u * p + 0u];
    const float q1 = quant[2u * p + 1u];
    const float lp1_m = log_prior[(p * 2u + 1u) * N + m];

    float4 d[4];
    #pragma unroll
    for (int k = 0; k < 4; k++) {
        const unsigned row = rh + 2u * k;
        const unsigned base = ((p * N + g * 8u + row) * N + g * 8u) * 8u + c * 4u;
        d[k] = __ldcs(reinterpret_cast<const float4*>(loglik + base));
    }
    float lp0r[4];
    #pragma unroll
    for (int k = 0; k < 4; k++)
        lp0r[k] = log_prior[(p * 2u + 0u) * N + g * 8u + rh + 2u * k];

    float rs[4];
    float wl = 0.0f;
    #pragma unroll
    for (int k = 0; k < 4; k++) {
        float h = ((d[k].x + d[k].y) + (d[k].z + d[k].w));
        float full = h + __shfl_xor_sync(0xffffffffu, h, 1);
        float llv = fminf(full * 0.125f, 0.0f);
        const unsigned row = rh + 2u * k;
        float dm = (row == ml) ? 0.0f : 1.0f;
        rs[k] = dm * pnotf(llv + lp1_m, q1);
        wl   += dm * pnotf(llv + lp0r[k], q0);
    }
    #pragma unroll
    for (int dd = 2; dd < 16; dd <<= 1) {
        #pragma unroll
        for (int k = 0; k < 4; k++)
            rs[k] += __shfl_xor_sync(0xffffffffu, rs[k], dd);
    }
    if (c == 0u) {
        #pragma unroll
        for (int k = 0; k < 4; k++) {
            const unsigned n = g * 8u + rh + 2u * k;
            out[(p * 2u + 0u) * N + n] = pnotf(rs[k], q1) + lp0r[k];
        }
    }
    wl += __shfl_xor_sync(0xffffffffu, wl, 16);
    if (rh == 0u && (c & 1u) == 0u) {
        out[(p * 2u + 1u) * N + m] = pnotf(wl, q0) + lp1_m;
    }
}

// ---------------------------------------------------------------- host side
typedef CUresult (*EncodeTiledFn)(
    CUtensorMap*, CUtensorMapDataType, cuuint32_t, void*,
    const cuuint64_t*, const cuuint64_t*, const cuuint32_t*, const cuuint32_t*,
    CUtensorMapInterleave, CUtensorMapSwizzle, CUtensorMapL2promotion,
    CUtensorMapFloatOOBfill);

extern "C" void kernel_launch(void* const* d_in, const int* in_sizes, int n_in,
                              void* d_out, int out_size) {
    const float* log_prior = (const float*)d_in[0];   // (64,2,512)
    const float* loglik    = (const float*)d_in[1];   // (64,512,512,8)
    const float* quant     = (const float*)d_in[2];   // (64,2)
    float* out = (float*)d_out;                       // (64,2,512)

    void* fn = nullptr;
    cudaDriverEntryPointQueryResult qr = cudaDriverEntryPointSymbolNotFound;
    cudaGetDriverEntryPoint("cuTensorMapEncodeTiled", &fn,
                            cudaEnableDefault, &qr);

    bool tma_ok = false;
    CUtensorMap tmap;
    if (fn && qr == cudaDriverEntryPointSuccess) {
        // Diagonal-linearized 4D view of loglik (float32):
        //   x: 64 floats (the 8x8xF tile row slice)
        //   y: 8 rows,   stride 16384 B (one n-row)
        //   z: 64 tiles, stride 131328 B (= 8*16384 + 256; diagonal step)
        //   w: 64 batch, stride 8388608 B (one p-slab)
        cuuint64_t dims[4]    = {64ull, 8ull, 64ull, 64ull};
        cuuint64_t strides[3] = {16384ull, 131328ull, 8388608ull};
        cuuint32_t box[4]     = {64u, 8u, 4u, 1u};
        cuuint32_t estr[4]    = {1u, 1u, 1u, 1u};
        CUresult r = ((EncodeTiledFn)fn)(
            &tmap, CU_TENSOR_MAP_DATA_TYPE_FLOAT32, 4, (void*)loglik,
            dims, strides, box, estr,
            CU_TENSOR_MAP_INTERLEAVE_NONE, CU_TENSOR_MAP_SWIZZLE_NONE,
            CU_TENSOR_MAP_L2_PROMOTION_L2_128B,
            CU_TENSOR_MAP_FLOAT_OOB_FILL_NONE);
        tma_ok = (r == CUDA_SUCCESS);
    }

    dim3 grid(16, 64);
    dim3 block(128);
    if (tma_ok) {
        relate_tma_kernel<<<grid, block>>>(tmap, log_prior, quant, out);
    } else {
        relate_batch_kernel<<<grid, block>>>(log_prior, loglik, quant, out);
    }
}